// round 7
// baseline (speedup 1.0000x reference)
#include <cuda_runtime.h>

#define TLEN   2048
#define BATCH  8192
#define STEPS  8
#define NT     (TLEN / STEPS)   // 256 tiles
#define RING   6                // smem ring depth
#define BLOCKT 64

__device__ __forceinline__ float frcp_fast(float x) {
    float r;
    asm("rcp.approx.f32 %0, %1;" : "=f"(r) : "f"(x));
    return r;
}
__device__ __forceinline__ float ftanh_fast(float x) {
    float r;
    asm("tanh.approx.f32 %0, %1;" : "=f"(r) : "f"(x));
    return r;
}

__device__ __forceinline__ void cpasync16(float4* dst, const float4* src) {
    unsigned d = (unsigned)__cvta_generic_to_shared(dst);
    asm volatile("cp.async.cg.shared.global [%0], [%1], 16;" :: "r"(d), "l"(src) : "memory");
}
__device__ __forceinline__ void cp_commit() {
    asm volatile("cp.async.commit_group;" ::: "memory");
}
__device__ __forceinline__ void cp_wait4() {
    asm volatile("cp.async.wait_group 4;" ::: "memory");
}

__shared__ float4 g_buf[RING][6][BLOCKT];   // 36 KB

__device__ __forceinline__ void issue_tile(int tile, int slot, int lane,
                                           const float4* p4, const float4* h4, const float4* s4)
{
    cpasync16(&g_buf[slot][0][lane], p4 + 2 * tile + 0);
    cpasync16(&g_buf[slot][1][lane], p4 + 2 * tile + 1);
    cpasync16(&g_buf[slot][2][lane], h4 + 2 * tile + 0);
    cpasync16(&g_buf[slot][3][lane], h4 + 2 * tile + 1);
    cpasync16(&g_buf[slot][4][lane], s4 + 2 * tile + 0);
    cpasync16(&g_buf[slot][5][lane], s4 + 2 * tile + 1);
    cp_commit();
}

// 4 EKF steps from one (p,h,s) float4 triple. Carried chain:
// S@12 -> rcp@28 -> {p00,p01,p11}@32; transform is off-chain.
__device__ __forceinline__ void steps4(const float4& pv, const float4& hv, const float4& sv,
                                       float& p00, float& p01, float& p11,
                                       float& x0, float& x1,
                                       float4* o4)
{
    const float zz[4] = {pv.x, pv.y, pv.z, pv.w};
    const float hh[4] = {hv.x, hv.y, hv.z, hv.w};
    const float ss[4] = {sv.x, sv.y, sv.z, sv.w};

    float4 o;
    #pragma unroll
    for (int j = 0; j < 4; j++) {
        // ---- transform (off-chain) ----
        // rho = 0.5 + 0.5*sigmoid(10(h-0.5)) = 0.75 + 0.25*tanh(5h-2.5); a = dt*rho
        const float a  = fmaf(0.25f, ftanh_fast(fmaf(5.0f, hh[j], -2.5f)), 0.75f);
        const float r  = fmaxf(100.0f * ss[j], 1.0f);   // scale
        const float q  = 0.1f * r;
        const float qs = 1.1f * r;                      // q + scale
        const float r2 = r * r;

        // ---- carried chain ----
        const float p01n = fmaf(a, p11, p01);
        const float X    = fmaf(a, p01, p00 + qs);
        const float S    = fmaf(a, p01n, X);            // P_pred00 + scale
        const float Sinv = frcp_fast(S);                // S >= 1

        // rcp-shadow work
        const float rm   = p01n * r;
        const float n2   = p01n * p01n;
        const float p11n = p11 + q;
        const float xp0  = fmaf(a, x1, x0);
        const float y    = zz[j] - xp0;

        const float K0 = fmaf(-r, Sinv, 1.0f);          // 1 - r/S
        const float K1 = p01n * Sinv;

        p00 = fmaf(-r2, Sinv, r);                       // r - r^2/S
        p01 = rm * Sinv;
        p11 = fmaf(-n2, Sinv, p11n);
        x0  = fmaf(K0, y, xp0);
        x1  = fmaf(K1, y, x1);

        if ((j & 1) == 0) { o.x = x0; o.y = x1; }
        else              { o.z = x0; o.w = x1; o4[j >> 1] = o; }
    }
}

// process one 8-step tile, reading the smem slot in two halves to keep
// the live register set small (no spills)
__device__ __forceinline__ void tile8_smem(int slot, int lane,
                                           float& p00, float& p01, float& p11,
                                           float& x0, float& x1,
                                           float4* o4)
{
    {
        const float4 pv = g_buf[slot][0][lane];
        const float4 hv = g_buf[slot][2][lane];
        const float4 sv = g_buf[slot][4][lane];
        steps4(pv, hv, sv, p00, p01, p11, x0, x1, o4);
    }
    {
        const float4 pv = g_buf[slot][1][lane];
        const float4 hv = g_buf[slot][3][lane];
        const float4 sv = g_buf[slot][5][lane];
        steps4(pv, hv, sv, p00, p01, p11, x0, x1, o4 + 2);
    }
}

__global__ void __launch_bounds__(BLOCKT, 1)   // unlock full register budget: no spills
ekf_kernel(const float* __restrict__ price,
           const float* __restrict__ hurst,
           const float* __restrict__ sigv,
           float* __restrict__ out)
{
    const int lane = threadIdx.x;
    const int b = blockIdx.x * BLOCKT + lane;

    const float4* __restrict__ p4 = (const float4*)(price + (size_t)b * TLEN);
    const float4* __restrict__ h4 = (const float4*)(hurst + (size_t)b * TLEN);
    const float4* __restrict__ s4 = (const float4*)(sigv  + (size_t)b * TLEN);
    float4* __restrict__ o4 = (float4*)(out + (size_t)b * TLEN * 2);

    // prologue: issue tiles 0..4, wait so tile 0 is resident
    #pragma unroll
    for (int t = 0; t < RING - 1; t++)
        issue_tile(t, t, lane, p4, h4, s4);
    cp_wait4();

    // initial state (dt = 1) from tile 0 in smem
    const float4 pz = g_buf[0][0][lane];
    float x0 = pz.x;
    float x1 = pz.y - pz.x;
    float p00 = 1.0f, p01 = 0.0f, p11 = 1.0f;

    #pragma unroll 1
    for (int t = 0; t < NT; t++) {
        const int it = t + RING - 1;
        issue_tile((it < NT) ? it : (NT - 1), it % RING, lane, p4, h4, s4);
        cp_wait4();                     // <=4 groups pending -> tile t (and t+1) resident
        tile8_smem(t % RING, lane, p00, p01, p11, x0, x1, o4 + 4 * t);
    }
}

extern "C" void kernel_launch(void* const* d_in, const int* in_sizes, int n_in,
                              void* d_out, int out_size)
{
    const float* price = (const float*)d_in[0];
    const float* hurst = (const float*)d_in[1];
    const float* sigv  = (const float*)d_in[2];
    float* out = (float*)d_out;

    ekf_kernel<<<BATCH / BLOCKT, BLOCKT>>>(price, hurst, sigv, out);
}